// round 4
// baseline (speedup 1.0000x reference)
#include <cuda_runtime.h>
#include <cstdint>

// out[b][f][s] = x[b][s] * w[f][s] + bias[f][s]
// B=128, F=256, S=4096  -> out = 134,217,728 floats (512 MiB). Store-bound.

#define BATCH_N   128
#define FILT_N    256
#define SEQ_N     4096
#define SEQ_V4    (SEQ_N / 4)          // 1024 float4 per row
#define TOTAL_V4  ((size_t)BATCH_N * FILT_N * SEQ_V4)  // 33,554,432

__global__ void __launch_bounds__(256) dense_filter_expand_kernel(
    const float4* __restrict__ x4,     // [BATCH, SEQ_V4]
    const float4* __restrict__ w4,     // [FILT,  SEQ_V4]
    const float4* __restrict__ b4,     // [FILT,  SEQ_V4]
    float4* __restrict__ out4)         // [BATCH, FILT, SEQ_V4]
{
    size_t i = (size_t)blockIdx.x * blockDim.x + threadIdx.x;
    // i = ((b*FILT + f)*SEQ_V4 + s4)
    unsigned s4 = (unsigned)(i & (SEQ_V4 - 1));
    unsigned fb = (unsigned)(i >> 10);          // b*FILT + f
    unsigned f  = fb & (FILT_N - 1);
    unsigned b  = fb >> 8;

    float4 xv = x4[(size_t)b * SEQ_V4 + s4];
    float4 wv = w4[(size_t)f * SEQ_V4 + s4];
    float4 bv = b4[(size_t)f * SEQ_V4 + s4];

    float4 o;
    o.x = fmaf(xv.x, wv.x, bv.x);
    o.y = fmaf(xv.y, wv.y, bv.y);
    o.z = fmaf(xv.z, wv.z, bv.z);
    o.w = fmaf(xv.w, wv.w, bv.w);

    out4[i] = o;
}

extern "C" void kernel_launch(void* const* d_in, const int* in_sizes, int n_in,
                              void* d_out, int out_size)
{
    const float4* x4 = (const float4*)d_in[0];  // inputs [128,1,4096] fp32
    const float4* w4 = (const float4*)d_in[1];  // w      [256,4096]   fp32
    const float4* b4 = (const float4*)d_in[2];  // b      [256,4096]   fp32
    float4* out4 = (float4*)d_out;              // out    [128,256,4096] fp32

    const int threads = 256;
    const size_t blocks = TOTAL_V4 / threads;   // 131072
    dense_filter_expand_kernel<<<(unsigned)blocks, threads>>>(x4, w4, b4, out4);
}

// round 7
// speedup vs baseline: 1.3606x; 1.3606x over previous
#include <cuda_runtime.h>
#include <cstdint>

// out[b][f][s] = x[b][s] * w[f][s] + bias[f][s]
// B=128, F=256, S=4096. Store-bound target; reduce L1 transactions by
// reusing w/bias across UB=4 batches per thread.

#define BATCH_N   128
#define FILT_N    256
#define SEQ_N     4096
#define SEQ_V4    (SEQ_N / 4)              // 1024 float4 per row
#define UB        4                        // batches per thread
#define BGROUPS   (BATCH_N / UB)           // 32

__global__ void __launch_bounds__(256) dense_filter_expand_kernel(
    const float4* __restrict__ x4,     // [BATCH, SEQ_V4]
    const float4* __restrict__ w4,     // [FILT,  SEQ_V4]
    const float4* __restrict__ b4,     // [FILT,  SEQ_V4]
    float4* __restrict__ out4)         // [BATCH, FILT, SEQ_V4]
{
    // i covers (bg, f, s4): s4 fastest for coalescing
    unsigned i  = blockIdx.x * blockDim.x + threadIdx.x;
    unsigned s4 = i & (SEQ_V4 - 1);
    unsigned f  = (i >> 10) & (FILT_N - 1);
    unsigned bg = i >> 18;                 // 0..31
    unsigned b0 = bg * UB;

    size_t fs = ((size_t)f << 10) + s4;
    float4 wv = w4[fs];
    float4 bv = b4[fs];

    #pragma unroll
    for (int u = 0; u < UB; u++) {
        unsigned b = b0 + u;
        float4 xv = x4[((size_t)b << 10) + s4];
        float4 o;
        o.x = fmaf(xv.x, wv.x, bv.x);
        o.y = fmaf(xv.y, wv.y, bv.y);
        o.z = fmaf(xv.z, wv.z, bv.z);
        o.w = fmaf(xv.w, wv.w, bv.w);
        // streaming store: don't let the 512MB output stream thrash L2,
        // keeping x/w/bias resident for later waves
        __stcs(&out4[(((size_t)b * FILT_N + f) << 10) + s4], o);
    }
}

extern "C" void kernel_launch(void* const* d_in, const int* in_sizes, int n_in,
                              void* d_out, int out_size)
{
    const float4* x4 = (const float4*)d_in[0];
    const float4* w4 = (const float4*)d_in[1];
    const float4* b4 = (const float4*)d_in[2];
    float4* out4 = (float4*)d_out;

    const int threads = 256;
    const unsigned total = (unsigned)FILT_N * SEQ_V4 * BGROUPS;  // 8,388,608
    dense_filter_expand_kernel<<<total / threads, threads>>>(x4, w4, b4, out4);
}